// round 15
// baseline (speedup 1.0000x reference)
#include <cuda_runtime.h>

#define HW 50176
#define W_ 224
#define H_ 224
#define SEGS 8
#define SEG_ROWS 28          // 224 / 8
#define QPR 56               // quads per row (224/4)
#define RG  56               // 4-row groups per plane (224/4)

__device__ float g_part[1024 * SEGS];   // per-(image,segment) partial sums
__device__ float g_gm[1024];            // per-image gray mean
__device__ int   g_cnt[1024];           // arrival tickets (zero-init, self-resetting)

// ---------------------------------------------------------------------------
// Kernel 1: R10 reduce byte-for-byte. FROZEN accumulation ORDER (fixes gm's
// fp value -> solarize flips). Proven 28-29us.
// ---------------------------------------------------------------------------
__global__ void __launch_bounds__(256)
reduce_kernel(const float* __restrict__ x,
              const float* __restrict__ mean,
              const float* __restrict__ stdv) {
    const int b = blockIdx.x >> 3;
    const int s = blockIdx.x & 7;
    const float* p = x + (size_t)b * 3 * HW + s * SEG_ROWS * W_;

    const float gw0 = 0.299f * stdv[0];
    const float gw1 = 0.587f * stdv[1];
    const float gw2 = 0.114f * stdv[2];

    const int npix = SEG_ROWS * W_ / 4;   // 1568 quads
    float acc = 0.f;

    int i = threadIdx.x;
    float4 a0 = *(const float4*)(p + i * 4);
    float4 a1 = *(const float4*)(p + HW + i * 4);
    float4 a2 = *(const float4*)(p + 2 * HW + i * 4);
    float4 b0 = *(const float4*)(p + (i + 256) * 4);
    float4 b1 = *(const float4*)(p + HW + (i + 256) * 4);
    float4 b2 = *(const float4*)(p + 2 * HW + (i + 256) * 4);

    while (i < npix) {
        const int pf = i + 512;            // distance-2 prefetch
        float4 c0, c1, c2;
        if (pf < npix) {
            c0 = *(const float4*)(p + pf * 4);
            c1 = *(const float4*)(p + HW + pf * 4);
            c2 = *(const float4*)(p + 2 * HW + pf * 4);
        }

        const int pix = i * 4;
        const int lr = pix / W_;
        const int cc0 = pix - lr * W_;
        const int gr = s * SEG_ROWS + lr;
        const float ny = (gr == 0 || gr == H_ - 1) ? 2.f : 3.f;

        float e0[4] = {a0.x, a0.y, a0.z, a0.w};
        float e1[4] = {a1.x, a1.y, a1.z, a1.w};
        float e2[4] = {a2.x, a2.y, a2.z, a2.w};

        if (cc0 != 0 && cc0 != W_ - 4) {
            const float coef = 0.64f + 0.36f * (ny * 3.f + 4.f) * (1.f / 13.f);
#pragma unroll
            for (int j = 0; j < 4; j++) {
                const float gx = gw0 * e0[j] + gw1 * e1[j] + gw2 * e2[j];
                acc += coef * gx;
            }
        } else {
#pragma unroll
            for (int j = 0; j < 4; j++) {
                const int c = cc0 + j;
                const float nxw = (c == 0 || c == W_ - 1) ? 2.f : 3.f;
                const float coef = 0.64f + 0.36f * (ny * nxw + 4.f) * (1.f / 13.f);
                const float gx = gw0 * e0[j] + gw1 * e1[j] + gw2 * e2[j];
                acc += coef * gx;
            }
        }

        a0 = b0; a1 = b1; a2 = b2;
        b0 = c0; b1 = c1; b2 = c2;
        i += 256;
    }

    __shared__ float red[8];
    __shared__ bool amLast;
#pragma unroll
    for (int off = 16; off > 0; off >>= 1)
        acc += __shfl_down_sync(0xffffffffu, acc, off);
    const int lane = threadIdx.x & 31;
    const int warp = threadIdx.x >> 5;
    if (lane == 0) red[warp] = acc;
    __syncthreads();
    if (threadIdx.x == 0) {
        float t = 0.f;
#pragma unroll
        for (int w = 0; w < 8; w++) t += red[w];
        g_part[blockIdx.x] = t;
        __threadfence();
        const int old = atomicAdd(&g_cnt[b], 1);
        amLast = (old == SEGS - 1);
    }
    __syncthreads();
    if (amLast && threadIdx.x == 0) {
        __threadfence();
        float ps = 0.f;
#pragma unroll
        for (int k = 0; k < SEGS; k++) ps += g_part[b * SEGS + k];
        const double SC = 0.64 * (double)HW + 0.36 * (448900.0 + 4.0 * HW) / 13.0;
        const float cm = 0.299f * mean[0] + 0.587f * mean[1] + 0.114f * mean[2];
        g_gm[b] = (ps + cm * (float)SC) * (1.0f / (float)HW);
        g_cnt[b] = 0;                      // reset for next graph replay
    }
}

// ---------------------------------------------------------------------------
// Kernel 2: main with column-sum shuffles. Neighbor column sums are obtained
// by shuffling THIS lane's window sums (bitwise-identical values and addition
// order to the old L/R-register scheme), deleting the L[6]/R[6] registers and
// 4 shuffles. Edge lanes keep the predicated scalar-load path.
// ---------------------------------------------------------------------------
__global__ void __launch_bounds__(256)
main_kernel(const float* __restrict__ x,
            const float* __restrict__ mean,
            const float* __restrict__ stdv,
            float* __restrict__ out,
            int nplanes) {
    const int idx = blockIdx.x * 256 + threadIdx.x;
    const int q = idx % QPR;                  // column quad 0..55
    const int t2 = idx / QPR;
    const int rg = t2 % RG;                   // row group 0..55
    int plane = t2 / RG;
    if (plane >= nplanes) return;
    plane = nplanes - 1 - plane;              // reverse traversal for L2 reuse

    const int b = plane / 3;
    const int ch = plane - b * 3;
    const float m = mean[ch];
    const float sd = stdv[ch];
    const float inv_sd = 1.0f / sd;
    const float nmo = -m * inv_sd;
    const float gm = g_gm[b];

    const float C1 = (float)(0.4096 * (0.64 + 1.44 / 13.0));
    const float C2 = (float)(0.4096 * 0.36 / 13.0);
    const float G  = (float)(0.64 * 0.36) * gm;

    const float* p = x + (size_t)plane * HW;
    const int c4 = q * 4;
    const int r0 = rg * 4;
    const unsigned lane = threadIdx.x & 31;

    // ---- 6 source rows (r0-1 .. r0+4), front-batched loads, affine ----
    float4 v[6];
#pragma unroll
    for (int k = 0; k < 6; k++) {
        const int row = r0 - 1 + k;
        if (row >= 0 && row < H_) {
            float4 u = *(const float4*)(p + row * W_ + c4);
            v[k].x = fmaf(u.x, sd, m);
            v[k].y = fmaf(u.y, sd, m);
            v[k].z = fmaf(u.z, sd, m);
            v[k].w = fmaf(u.w, sd, m);
        } else {
            v[k] = make_float4(0.f, 0.f, 0.f, 0.f);
        }
    }

    // ---- edge-lane halos only (lane 0 / lane 31 at non-image-border) ----
    float hL[6], hR[6];
    const bool needL = (lane == 0) && (q != 0);
    const bool needR = (lane == 31) && (q != QPR - 1);
    if (needL) {
#pragma unroll
        for (int k = 0; k < 6; k++) {
            const int row = r0 - 1 + k;
            hL[k] = (row >= 0 && row < H_) ? fmaf(p[row * W_ + c4 - 1], sd, m) : 0.f;
        }
    }
    if (needR) {
#pragma unroll
        for (int k = 0; k < 6; k++) {
            const int row = r0 - 1 + k;
            hR[k] = (row >= 0 && row < H_) ? fmaf(p[row * W_ + c4 + 4], sd, m) : 0.f;
        }
    }

    // ---- 4 output rows: window column sums + neighbor sums via shuffle ----
    float* ob = out + (size_t)plane * HW + r0 * W_ + c4;

#pragma unroll
    for (int o = 0; o < 4; o++) {
        const float cs1 = v[o].x + v[o + 1].x + v[o + 2].x;
        const float cs2 = v[o].y + v[o + 1].y + v[o + 2].y;
        const float cs3 = v[o].z + v[o + 1].z + v[o + 2].z;
        const float cs4 = v[o].w + v[o + 1].w + v[o + 2].w;

        // neighbor window sums: identical values + addition order as the old
        // L/R scheme (neighbor computed cs4/cs1 from the same floats)
        float csL = __shfl_up_sync(0xffffffffu, cs4, 1);
        float csR = __shfl_down_sync(0xffffffffu, cs1, 1);
        if (q == 0)              csL = 0.f;
        else if (lane == 0)      csL = hL[o] + hL[o + 1] + hL[o + 2];
        if (q == QPR - 1)        csR = 0.f;
        else if (lane == 31)     csR = hR[o] + hR[o + 1] + hR[o + 2];

        const float cen[4] = {v[o + 1].x, v[o + 1].y, v[o + 1].z, v[o + 1].w};
        const float tot[4] = {csL + cs1 + cs2, cs1 + cs2 + cs3,
                              cs2 + cs3 + cs4, cs3 + cs4 + csR};

        float4 ov;
        float* op = (float*)&ov;
#pragma unroll
        for (int j = 0; j < 4; j++) {
            const float y2 = fmaf(cen[j], C1, fmaf(tot[j], C2, G));
            const float z = (y2 < 0.3f) ? y2 : 1.0f - y2;
            op[j] = fmaf(z, inv_sd, nmo);
        }
        __stwt((float4*)(ob + o * W_), ov);    // write-through, no L2 allocate
    }
}

extern "C" void kernel_launch(void* const* d_in, const int* in_sizes, int n_in,
                              void* d_out, int out_size) {
    const float* x    = (const float*)d_in[0];
    const float* mean = (const float*)d_in[1];
    const float* stdv = (const float*)d_in[2];
    float* out = (float*)d_out;

    const int B = in_sizes[0] / (3 * HW);
    const int nplanes = B * 3;

    reduce_kernel<<<B * SEGS, 256>>>(x, mean, stdv);

    const int total = nplanes * RG * QPR;
    main_kernel<<<(total + 255) / 256, 256>>>(x, mean, stdv, out, nplanes);
}